// round 1
// baseline (speedup 1.0000x reference)
#include <cuda_runtime.h>
#include <math.h>

// Problem constants
#define NN 768
#define HH 12
#define CC 16
#define PQ 4
#define PV 8
#define CZ 128
#define CS 384
// proj concat layout: [q 192 | kv 384 | qp_raw 144 | kvp_raw 432] = 1152
#define PROJ_N 1152
#define FEAT_N 2112   // [o 192 | ptx 96 | pty 96 | ptz 96 | ptnorm 96 | opair 1536]

// ---------------- scratch (static device allocations) ----------------
__device__ float g_proj[NN * PROJ_N];
__device__ float g_k[NN * 192];
__device__ float g_v[NN * 192];
__device__ float g_qpts[NN * 144];   // [n][h*4+p][3]
__device__ float g_kpts[NN * 144];
__device__ float g_vpts[NN * 288];   // [n][h*8+p][3]
__device__ float g_a[(size_t)NN * HH * NN];  // [i][h][j]
__device__ float g_optg[NN * 288];   // o_pt in global frame
__device__ float g_feats[NN * FEAT_N];

// ---------------- K1/K7: segmented tiled GEMM  out = A @ W + bias ----------------
// BM=64, BN=48, BK=16, 256 threads, 4x3 register tile. Segment boundaries must be
// multiples of 48 (they are: 192, 576, 720, 1152; and 384 for the final GEMM).
__global__ __launch_bounds__(256) void gemm_seg_kernel(
    const float* __restrict__ A, int K,
    const float* __restrict__ w0, const float* __restrict__ w1,
    const float* __restrict__ w2, const float* __restrict__ w3,
    const float* __restrict__ b0, const float* __restrict__ b1,
    const float* __restrict__ b2, const float* __restrict__ b3,
    int e0, int e1, int e2, int e3,
    float* __restrict__ out, int ldo)
{
    __shared__ float As[16][64];
    __shared__ float Bs[16][48];

    const int m0 = blockIdx.y * 64;
    const int n0 = blockIdx.x * 48;

    const float* W; const float* bias; int base, segN;
    if (n0 < e0)      { W = w0; bias = b0; base = 0;  segN = e0; }
    else if (n0 < e1) { W = w1; bias = b1; base = e0; segN = e1 - e0; }
    else if (n0 < e2) { W = w2; bias = b2; base = e1; segN = e2 - e1; }
    else              { W = w3; bias = b3; base = e2; segN = e3 - e2; }

    const int t = threadIdx.x;
    const int trow = t >> 4;          // 0..15 -> 4 rows each
    const int tcol = t & 15;          // 0..15 -> 3 cols each
    const int ar  = t >> 2;           // A-load row 0..63
    const int ac4 = (t & 3) * 4;      // A-load k offset
    const int bk  = t >> 4;           // B-load k row
    const int bn  = (t & 15) * 3;     // B-load col

    float acc[4][3] = {};

    for (int k0 = 0; k0 < K; k0 += 16) {
        float4 av = *(const float4*)&A[(size_t)(m0 + ar) * K + k0 + ac4];
        As[ac4 + 0][ar] = av.x; As[ac4 + 1][ar] = av.y;
        As[ac4 + 2][ar] = av.z; As[ac4 + 3][ar] = av.w;
        const float* wp = W + (size_t)(k0 + bk) * segN + (n0 - base) + bn;
        Bs[bk][bn + 0] = wp[0]; Bs[bk][bn + 1] = wp[1]; Bs[bk][bn + 2] = wp[2];
        __syncthreads();
        #pragma unroll
        for (int kk = 0; kk < 16; kk++) {
            float4 a4 = *(const float4*)&As[kk][trow * 4];
            float bb0 = Bs[kk][tcol * 3 + 0];
            float bb1 = Bs[kk][tcol * 3 + 1];
            float bb2 = Bs[kk][tcol * 3 + 2];
            acc[0][0] += a4.x * bb0; acc[0][1] += a4.x * bb1; acc[0][2] += a4.x * bb2;
            acc[1][0] += a4.y * bb0; acc[1][1] += a4.y * bb1; acc[1][2] += a4.y * bb2;
            acc[2][0] += a4.z * bb0; acc[2][1] += a4.z * bb1; acc[2][2] += a4.z * bb2;
            acc[3][0] += a4.w * bb0; acc[3][1] += a4.w * bb1; acc[3][2] += a4.w * bb2;
        }
        __syncthreads();
    }
    #pragma unroll
    for (int r = 0; r < 4; r++) {
        #pragma unroll
        for (int c = 0; c < 3; c++) {
            int n = n0 + tcol * 3 + c;
            out[(size_t)(m0 + trow * 4 + r) * ldo + n] = acc[r][c] + bias[(n - base)];
        }
    }
}

// ---------------- K2: split k/v, rotate+translate points ----------------
__global__ __launch_bounds__(256) void prep_kernel(
    const float* __restrict__ rot, const float* __restrict__ trans)
{
    const int n = blockIdx.x;
    const int t = threadIdx.x;
    const float* pr = &g_proj[(size_t)n * PROJ_N];

    if (t < 192) {
        int h = t >> 4, cc = t & 15;
        g_k[n * 192 + t] = pr[192 + h * 32 + cc];
        g_v[n * 192 + t] = pr[192 + h * 32 + 16 + cc];
    }
    float r[9], tr[3];
    #pragma unroll
    for (int e = 0; e < 9; e++) r[e] = rot[n * 9 + e];
    tr[0] = trans[n * 3 + 0]; tr[1] = trans[n * 3 + 1]; tr[2] = trans[n * 3 + 2];

    if (t < 48) {  // q_pts: raw cols [576,720) laid out (xyz, hp)
        float p0 = pr[576 + 0 * 48 + t];
        float p1 = pr[576 + 1 * 48 + t];
        float p2 = pr[576 + 2 * 48 + t];
        #pragma unroll
        for (int ii = 0; ii < 3; ii++) {
            float o = r[ii * 3 + 0] * p0 + r[ii * 3 + 1] * p1 + r[ii * 3 + 2] * p2 + tr[ii];
            g_qpts[n * 144 + t * 3 + ii] = o;
        }
    }
    if (t < 144) {  // kv_pts: raw cols [720,1152)
        float p0 = pr[720 + 0 * 144 + t];
        float p1 = pr[720 + 1 * 144 + t];
        float p2 = pr[720 + 2 * 144 + t];
        int h = t / 12, p = t % 12;
        #pragma unroll
        for (int ii = 0; ii < 3; ii++) {
            float o = r[ii * 3 + 0] * p0 + r[ii * 3 + 1] * p1 + r[ii * 3 + 2] * p2 + tr[ii];
            if (p < 4) g_kpts[n * 144 + (h * 4 + p) * 3 + ii] = o;
            else       g_vpts[n * 288 + (h * 8 + (p - 4)) * 3 + ii] = o;
        }
    }
}

// ---------------- K3: logits (z-bias inline) + softmax, one block per query ----------------
// dynamic smem layout (floats):
//  s_logit 12*768 | s_w 768 | s_q 192 | s_qp 144 | s_wbT 12*128 | s_z 64*132
#define K3_SMEM_FLOATS (12*768 + 768 + 192 + 144 + 12*128 + 64*132)

__global__ __launch_bounds__(256) void logits_kernel(
    const float* __restrict__ z, const float* __restrict__ ss,
    const float* __restrict__ mask,
    const float* __restrict__ w_b, const float* __restrict__ b_b,
    const float* __restrict__ head_w)
{
    extern __shared__ float sm[];
    float* s_logit = sm;                    // [h][j]
    float* s_w     = s_logit + 12 * 768;
    float* s_q     = s_w + 768;
    float* s_qp    = s_q + 192;
    float* s_wbT   = s_qp + 144;            // [h][c]
    float* s_z     = s_wbT + 1536;          // [jj][132]
    __shared__ float s_hw[12], s_bb[12], s_maski;

    const int i = blockIdx.x;
    const int t = threadIdx.x;

    for (int idx = t; idx < 192; idx += 256) s_q[idx] = g_proj[(size_t)i * PROJ_N + idx];
    for (int idx = t; idx < 144; idx += 256) s_qp[idx] = g_qpts[i * 144 + idx];
    for (int idx = t; idx < 1536; idx += 256) {
        int h = idx >> 7, c = idx & 127;
        s_wbT[idx] = w_b[c * 12 + h];
    }
    for (int idx = t; idx < 768; idx += 256)
        s_w[idx] = __expf(ss[(size_t)i * 768 + idx]) - 0.99f;
    if (t < 12) {
        float x = head_w[t];
        float sp = (x > 20.f) ? x : log1pf(__expf(x));
        s_hw[t] = sp * 0.13608276348795434f;   // sqrt(1/54)
        s_bb[t] = b_b[t];
    }
    if (t == 0) s_maski = mask[i];
    __syncthreads();
    const float mask_i = s_maski;

    const int lc = (t & 31) * 4;   // z staging
    const int jr = t >> 5;
    const int hh = t & 3;          // compute mapping
    const int jq = t >> 2;         // jj 0..63

    for (int j0 = 0; j0 < 768; j0 += 64) {
        #pragma unroll
        for (int r = 0; r < 8; r++) {
            int jj = jr + r * 8;
            float4 zv = *(const float4*)&z[((size_t)(i * 768 + j0 + jj)) * 128 + lc];
            *(float4*)&s_z[jj * 132 + lc] = zv;
        }
        __syncthreads();

        const int j = j0 + jq;
        const float maskterm = 100000.f * (mask_i * mask[j] - 1.f);
        const float* zr = &s_z[jq * 132];

        // bias dot-products for h = hh, hh+4, hh+8 (z loaded once)
        float a0[3] = {}, a1[3] = {}, a2[3] = {}, a3[3] = {};
        #pragma unroll 8
        for (int c = 0; c < 128; c += 4) {
            float4 zv = *(const float4*)&zr[c];
            #pragma unroll
            for (int q = 0; q < 3; q++) {
                float4 wv = *(const float4*)&s_wbT[(hh + 4 * q) * 128 + c];
                a0[q] += zv.x * wv.x; a1[q] += zv.y * wv.y;
                a2[q] += zv.z * wv.z; a3[q] += zv.w * wv.w;
            }
        }
        #pragma unroll
        for (int q = 0; q < 3; q++) {
            const int h = hh + 4 * q;
            float bias = (a0[q] + a1[q]) + (a2[q] + a3[q]) + s_bb[h];
            // qk
            float qk0 = 0, qk1 = 0, qk2 = 0, qk3 = 0;
            const float* kr = &g_k[j * 192 + h * 16];
            const float* qr = &s_q[h * 16];
            #pragma unroll
            for (int c = 0; c < 16; c += 4) {
                float4 kv = *(const float4*)&kr[c];
                qk0 += qr[c + 0] * kv.x; qk1 += qr[c + 1] * kv.y;
                qk2 += qr[c + 2] * kv.z; qk3 += qr[c + 3] * kv.w;
            }
            float qk = (qk0 + qk1) + (qk2 + qk3);
            // point distances
            float pts = 0.f;
            const float* kp = &g_kpts[j * 144 + h * 12];
            const float* qp = &s_qp[h * 12];
            #pragma unroll
            for (int e = 0; e < 12; e++) {
                float d = qp[e] - kp[e];
                pts += d * d;
            }
            float logit = qk * 0.14433756729740643f          // sqrt(1/48)
                        + 0.5773502691896258f * bias          // sqrt(1/3)
                        - 0.5f * s_hw[h] * pts
                        + maskterm;
            s_logit[h * 768 + j] = logit;
        }
        __syncthreads();
    }

    // softmax per head with ss-derived weights
    const int w = t >> 5, lane = t & 31;
    for (int h = w; h < 12; h += 8) {
        const float* lr = &s_logit[h * 768];
        float m = -1e30f;
        for (int j = lane; j < 768; j += 32) m = fmaxf(m, lr[j]);
        #pragma unroll
        for (int o = 16; o; o >>= 1) m = fmaxf(m, __shfl_xor_sync(0xffffffffu, m, o));
        float ssum = 0.f;
        for (int j = lane; j < 768; j += 32) ssum += __expf(lr[j] - m) * s_w[j];
        #pragma unroll
        for (int o = 16; o; o >>= 1) ssum += __shfl_xor_sync(0xffffffffu, ssum, o);
        float inv = 1.f / ssum;
        float* ar = &g_a[((size_t)i * 12 + h) * 768];
        for (int j = lane; j < 768; j += 32)
            ar[j] = __expf(lr[j] - m) * s_w[j] * inv;
    }
}

// ---------------- K4: o = a@v, o_pt(global) = a@v_pts ; 16 queries/block ----------------
__global__ __launch_bounds__(192) void ov_kernel()
{
    __shared__ float s_a[16 * 12 * 16];   // [q][h][jj]
    __shared__ float s_vv[16 * 12 * 40];  // [jj][h][0..15 = v, 16..39 = v_pts]

    const int q0 = blockIdx.x * 16;
    const int t = threadIdx.x;
    const int qg = t / 48;           // 0..3 (4 queries each)
    const int rem = t % 48;
    const int h = rem >> 2;          // 0..11
    const int cs = rem & 3;          // 0..3 (10 outputs each)

    float acc[4][10] = {};

    for (int j0 = 0; j0 < 768; j0 += 16) {
        for (int idx = t; idx < 3072; idx += 192) {
            int q = idx / 192; int r2 = idx % 192; int hhh = r2 >> 4; int jj = r2 & 15;
            s_a[idx] = g_a[((size_t)(q0 + q) * 12 + hhh) * 768 + j0 + jj];
        }
        for (int idx = t; idx < 7680; idx += 192) {
            int jj = idx / 480; int r2 = idx % 480; int hhh = r2 / 40; int e = r2 % 40;
            s_vv[idx] = (e < 16) ? g_v[(j0 + jj) * 192 + hhh * 16 + e]
                                 : g_vpts[(j0 + jj) * 288 + hhh * 24 + (e - 16)];
        }
        __syncthreads();
        for (int jj = 0; jj < 16; jj++) {
            float av0 = s_a[((qg * 4 + 0) * 12 + h) * 16 + jj];
            float av1 = s_a[((qg * 4 + 1) * 12 + h) * 16 + jj];
            float av2 = s_a[((qg * 4 + 2) * 12 + h) * 16 + jj];
            float av3 = s_a[((qg * 4 + 3) * 12 + h) * 16 + jj];
            const float* vp = &s_vv[(jj * 12 + h) * 40 + cs * 10];
            #pragma unroll
            for (int u = 0; u < 10; u++) {
                float vv = vp[u];
                acc[0][u] += av0 * vv; acc[1][u] += av1 * vv;
                acc[2][u] += av2 * vv; acc[3][u] += av3 * vv;
            }
        }
        __syncthreads();
    }
    #pragma unroll
    for (int qq = 0; qq < 4; qq++) {
        int n = q0 + qg * 4 + qq;
        #pragma unroll
        for (int u = 0; u < 10; u++) {
            int e = cs * 10 + u;
            if (e < 16) g_feats[(size_t)n * FEAT_N + h * 16 + e] = acc[qq][u];
            else        g_optg[n * 288 + h * 24 + (e - 16)] = acc[qq][u];
        }
    }
}

// ---------------- K5: o_pair = a @ z (second z pass) ----------------
__global__ __launch_bounds__(256) void opair_kernel(const float* __restrict__ z)
{
    __shared__ float s_z[64 * 132];
    __shared__ float s_a2[12 * 64];

    const int i = blockIdx.x;
    const int t = threadIdx.x;
    const int c4 = (t & 31) * 4;
    const int hs = t >> 5;           // warp id 0..7; handles h=hs (+ h=hs+8 if hs<4)

    float ax0 = 0, ax1 = 0, ax2 = 0, ax3 = 0;
    float bx0 = 0, bx1 = 0, bx2 = 0, bx3 = 0;

    for (int j0 = 0; j0 < 768; j0 += 64) {
        #pragma unroll
        for (int r = 0; r < 8; r++) {
            int jj = (t >> 5) + r * 8;
            float4 zv = *(const float4*)&z[((size_t)(i * 768 + j0 + jj)) * 128 + c4];
            *(float4*)&s_z[jj * 132 + c4] = zv;
        }
        for (int idx = t; idx < 768; idx += 256) {
            int hhh = idx >> 6, jj = idx & 63;
            s_a2[idx] = g_a[((size_t)i * 12 + hhh) * 768 + j0 + jj];
        }
        __syncthreads();
        #pragma unroll 4
        for (int jj = 0; jj < 64; jj++) {
            float4 zv = *(const float4*)&s_z[jj * 132 + c4];
            float a0 = s_a2[hs * 64 + jj];
            ax0 += zv.x * a0; ax1 += zv.y * a0; ax2 += zv.z * a0; ax3 += zv.w * a0;
            if (hs < 4) {
                float a1 = s_a2[(hs + 8) * 64 + jj];
                bx0 += zv.x * a1; bx1 += zv.y * a1; bx2 += zv.z * a1; bx3 += zv.w * a1;
            }
        }
        __syncthreads();
    }
    float* fo = &g_feats[(size_t)i * FEAT_N + 576];
    fo[hs * 128 + c4 + 0] = ax0; fo[hs * 128 + c4 + 1] = ax1;
    fo[hs * 128 + c4 + 2] = ax2; fo[hs * 128 + c4 + 3] = ax3;
    if (hs < 4) {
        fo[(hs + 8) * 128 + c4 + 0] = bx0; fo[(hs + 8) * 128 + c4 + 1] = bx1;
        fo[(hs + 8) * 128 + c4 + 2] = bx2; fo[(hs + 8) * 128 + c4 + 3] = bx3;
    }
}

// ---------------- K6: inverse-rotate o_pt, norms, place into feats ----------------
__global__ __launch_bounds__(96) void optfinal_kernel(
    const float* __restrict__ rot, const float* __restrict__ trans)
{
    const int n = blockIdx.x;
    const int hp = threadIdx.x;   // 0..95
    float r[9], tr[3];
    #pragma unroll
    for (int e = 0; e < 9; e++) r[e] = rot[n * 9 + e];
    tr[0] = trans[n * 3 + 0]; tr[1] = trans[n * 3 + 1]; tr[2] = trans[n * 3 + 2];

    float gx = g_optg[n * 288 + hp * 3 + 0] - tr[0];
    float gy = g_optg[n * 288 + hp * 3 + 1] - tr[1];
    float gz = g_optg[n * 288 + hp * 3 + 2] - tr[2];
    // out[k] = sum_j rot[j][k] * g[j]
    float l0 = r[0] * gx + r[3] * gy + r[6] * gz;
    float l1 = r[1] * gx + r[4] * gy + r[7] * gz;
    float l2 = r[2] * gx + r[5] * gy + r[8] * gz;

    float* f = &g_feats[(size_t)n * FEAT_N];
    f[192 + hp] = l0;
    f[288 + hp] = l1;
    f[384 + hp] = l2;
    f[480 + hp] = sqrtf(l0 * l0 + l1 * l1 + l2 * l2 + 1e-8f);
}

// ---------------- launch ----------------
extern "C" void kernel_launch(void* const* d_in, const int* in_sizes, int n_in,
                              void* d_out, int out_size)
{
    const float* s       = (const float*)d_in[0];
    const float* z       = (const float*)d_in[1];
    const float* rot     = (const float*)d_in[2];
    const float* trans   = (const float*)d_in[3];
    const float* mask    = (const float*)d_in[4];
    const float* ss      = (const float*)d_in[5];
    const float* w_q     = (const float*)d_in[6];
    const float* b_q     = (const float*)d_in[7];
    const float* w_kv    = (const float*)d_in[8];
    const float* b_kv    = (const float*)d_in[9];
    const float* w_qp    = (const float*)d_in[10];
    const float* b_qp    = (const float*)d_in[11];
    const float* w_kvp   = (const float*)d_in[12];
    const float* b_kvp   = (const float*)d_in[13];
    const float* w_b     = (const float*)d_in[14];
    const float* b_b     = (const float*)d_in[15];
    const float* head_w  = (const float*)d_in[16];
    const float* w_out   = (const float*)d_in[17];
    const float* b_out   = (const float*)d_in[18];
    float* out = (float*)d_out;

    float* proj;  cudaGetSymbolAddress((void**)&proj, g_proj);
    float* feats; cudaGetSymbolAddress((void**)&feats, g_feats);

    static bool attr_done = false;
    if (!attr_done) {
        cudaFuncSetAttribute(logits_kernel,
                             cudaFuncAttributeMaxDynamicSharedMemorySize,
                             K3_SMEM_FLOATS * 4);
        attr_done = true;
    }

    // K1: projections  (768 x 1152 = s @ [w_q|w_kv|w_qp|w_kvp])
    gemm_seg_kernel<<<dim3(24, 12), 256>>>(
        s, CS, w_q, w_kv, w_qp, w_kvp, b_q, b_kv, b_qp, b_kvp,
        192, 576, 720, 1152, proj, PROJ_N);

    // K2: split k/v, rotate points
    prep_kernel<<<NN, 256>>>(rot, trans);

    // K3: logits + softmax (first z pass)
    logits_kernel<<<NN, 256, K3_SMEM_FLOATS * 4>>>(z, ss, mask, w_b, b_b, head_w);

    // K4: o and o_pt accumulation
    ov_kernel<<<NN / 16, 192>>>();

    // K5: o_pair (second z pass)
    opair_kernel<<<NN, 256>>>(z);

    // K6: finalize o_pt + norms
    optfinal_kernel<<<NN, 96>>>(rot, trans);

    // K7: output GEMM  (768 x 384 = feats @ w_out + b_out)
    gemm_seg_kernel<<<dim3(8, 12), 256>>>(
        feats, FEAT_N, w_out, w_out, w_out, w_out, b_out, b_out, b_out, b_out,
        384, 384, 384, 384, out, CS);
}

// round 3
// speedup vs baseline: 1.5043x; 1.5043x over previous
#include <cuda_runtime.h>
#include <math.h>

// Problem constants
#define NN 768
#define HH 12
#define CC 16
#define CZ 128
#define CS 384
#define PROJ_N 1152
#define FEAT_N 2112   // [o 192 | ptx 96 | pty 96 | ptz 96 | ptnorm 96 | opair 1536]

typedef unsigned long long ull;

// ---------------- f32x2 helpers ----------------
__device__ __forceinline__ void ffma2(ull& d, ull a, ull b) {
    asm("fma.rn.f32x2 %0, %1, %2, %0;" : "+l"(d) : "l"(a), "l"(b));
}
__device__ __forceinline__ void fmul2(ull& d, ull a) {
    asm("mul.rn.f32x2 %0, %0, %1;" : "+l"(d) : "l"(a));
}
__device__ __forceinline__ ull fadd2(ull a, ull b) {
    ull r; asm("add.rn.f32x2 %0, %1, %2;" : "=l"(r) : "l"(a), "l"(b)); return r;
}
__device__ __forceinline__ ull pack2(float x, float y) {
    ull r; asm("mov.b64 %0, {%1, %2};" : "=l"(r) : "f"(x), "f"(y)); return r;
}
__device__ __forceinline__ float2 unpack2(ull v) {
    float2 r; asm("mov.b64 {%0, %1}, %2;" : "=f"(r.x), "=f"(r.y) : "l"(v)); return r;
}

// ---------------- scratch ----------------
__device__ float g_proj[NN * PROJ_N];
__device__ float g_k[NN * 192];
__device__ float g_v[NN * 192];
__device__ float g_qpts[NN * 144];   // [n][h*4+p][3]
__device__ float g_kpts[NN * 144];
__device__ float g_vpts[NN * 288];   // [n][h*8+p][3]
__device__ float g_a[(size_t)NN * HH * NN];  // [i][h][j]
__device__ float g_optg[NN * 288];
__device__ float g_feats[NN * FEAT_N];

// ---------------- GEMM: out = A @ W + bias, segmented over N ----------------
// BM=32, BN=64, BK=16, 256 threads, 2x4 per thread.
__global__ __launch_bounds__(256) void gemm_kernel(
    const float* __restrict__ A, int K,
    const float* __restrict__ w0, const float* __restrict__ w1,
    const float* __restrict__ w2, const float* __restrict__ w3,
    const float* __restrict__ b0, const float* __restrict__ b1,
    const float* __restrict__ b2, const float* __restrict__ b3,
    int e0, int e1, int e2, int e3,
    float* __restrict__ out, int ldo)
{
    __shared__ float As[16][34];
    __shared__ float Bs[16][64];

    const int m0 = blockIdx.y * 32;
    const int n0 = blockIdx.x * 64;
    const int t = threadIdx.x;

    // B-load mapping (segment per column-quad; boundaries are multiples of 4)
    const int bkr = t >> 4;
    const int n   = n0 + (t & 15) * 4;
    const float* W; const float* bias; int base, segN;
    if (n < e0)      { W = w0; bias = b0; base = 0;  segN = e0; }
    else if (n < e1) { W = w1; bias = b1; base = e0; segN = e1 - e0; }
    else if (n < e2) { W = w2; bias = b2; base = e1; segN = e2 - e1; }
    else             { W = w3; bias = b3; base = e2; segN = e3 - e2; }

    const int ar  = t >> 2;
    const int ac4 = (t & 3) * 4;
    const int ty  = t >> 4;      // row pair
    const int tx  = t & 15;      // col quad

    float acc[2][4] = {};

    for (int k0 = 0; k0 < K; k0 += 16) {
        if (t < 128) {
            float4 av = *(const float4*)&A[(size_t)(m0 + ar) * K + k0 + ac4];
            As[ac4 + 0][ar] = av.x; As[ac4 + 1][ar] = av.y;
            As[ac4 + 2][ar] = av.z; As[ac4 + 3][ar] = av.w;
        }
        float4 bv = *(const float4*)&W[(size_t)(k0 + bkr) * segN + (n - base)];
        *(float4*)&Bs[bkr][(t & 15) * 4] = bv;
        __syncthreads();
        #pragma unroll
        for (int kk = 0; kk < 16; kk++) {
            float2 a2 = *(const float2*)&As[kk][ty * 2];
            float4 b4 = *(const float4*)&Bs[kk][tx * 4];
            acc[0][0] += a2.x * b4.x; acc[0][1] += a2.x * b4.y;
            acc[0][2] += a2.x * b4.z; acc[0][3] += a2.x * b4.w;
            acc[1][0] += a2.y * b4.x; acc[1][1] += a2.y * b4.y;
            acc[1][2] += a2.y * b4.z; acc[1][3] += a2.y * b4.w;
        }
        __syncthreads();
    }
    float4 bb = *(const float4*)&bias[n - base];
    #pragma unroll
    for (int r = 0; r < 2; r++) {
        float4 o;
        o.x = acc[r][0] + bb.x; o.y = acc[r][1] + bb.y;
        o.z = acc[r][2] + bb.z; o.w = acc[r][3] + bb.w;
        *(float4*)&out[(size_t)(m0 + ty * 2 + r) * ldo + n] = o;
    }
}

// ---------------- prep: split k/v, rotate+translate points ----------------
__global__ __launch_bounds__(256) void prep_kernel(
    const float* __restrict__ rot, const float* __restrict__ trans)
{
    const int nn = blockIdx.x;
    const int t = threadIdx.x;
    const float* pr = &g_proj[(size_t)nn * PROJ_N];

    if (t < 192) {
        int h = t >> 4, cc = t & 15;
        g_k[nn * 192 + t] = pr[192 + h * 32 + cc];
        g_v[nn * 192 + t] = pr[192 + h * 32 + 16 + cc];
    }
    float r[9], tr[3];
    #pragma unroll
    for (int e = 0; e < 9; e++) r[e] = rot[nn * 9 + e];
    tr[0] = trans[nn * 3 + 0]; tr[1] = trans[nn * 3 + 1]; tr[2] = trans[nn * 3 + 2];

    if (t < 48) {
        float p0 = pr[576 + 0 * 48 + t];
        float p1 = pr[576 + 1 * 48 + t];
        float p2 = pr[576 + 2 * 48 + t];
        #pragma unroll
        for (int ii = 0; ii < 3; ii++)
            g_qpts[nn * 144 + t * 3 + ii] =
                r[ii * 3 + 0] * p0 + r[ii * 3 + 1] * p1 + r[ii * 3 + 2] * p2 + tr[ii];
    }
    if (t < 144) {
        float p0 = pr[720 + 0 * 144 + t];
        float p1 = pr[720 + 1 * 144 + t];
        float p2 = pr[720 + 2 * 144 + t];
        int h = t / 12, p = t % 12;
        #pragma unroll
        for (int ii = 0; ii < 3; ii++) {
            float o = r[ii * 3 + 0] * p0 + r[ii * 3 + 1] * p1 + r[ii * 3 + 2] * p2 + tr[ii];
            if (p < 4) g_kpts[nn * 144 + (h * 4 + p) * 3 + ii] = o;
            else       g_vpts[nn * 288 + (h * 8 + (p - 4)) * 3 + ii] = o;
        }
    }
}

// ---------------- attn: logits + online softmax + o_pair, ONE z pass ----------------
// dyn smem floats: s_logit 9216 | s_z 8448 (64x132) | s_p 768 | s_w 768 | s_q 192 | s_qp 144 | s_wbT 1536
#define ATTN_SMEM_FLOATS (9216 + 8448 + 768 + 768 + 192 + 144 + 1536)

__global__ __launch_bounds__(256, 2) void attn_kernel(
    const float* __restrict__ z, const float* __restrict__ ss,
    const float* __restrict__ mask,
    const float* __restrict__ w_b, const float* __restrict__ b_b,
    const float* __restrict__ head_w)
{
    extern __shared__ float sm[];
    float* s_logit = sm;                    // [h][j] raw logits (full row)
    float* s_z     = s_logit + 9216;        // [jj][132]
    float* s_p     = s_z + 8448;            // [h][jj] tile probs*weights
    float* s_w     = s_p + 768;             // exp(ss)-0.99
    float* s_q     = s_w + 768;
    float* s_qp    = s_q + 192;
    float* s_wbT   = s_qp + 144;            // [h][c]
    __shared__ float s_m[12], s_s[12], s_scale[12], s_inv[12], s_bb[12], s_hw[12], s_maski;

    const int i = blockIdx.x;
    const int t = threadIdx.x;

    for (int idx = t; idx < 192; idx += 256) s_q[idx] = g_proj[(size_t)i * PROJ_N + idx];
    for (int idx = t; idx < 144; idx += 256) s_qp[idx] = g_qpts[i * 144 + idx];
    for (int idx = t; idx < 1536; idx += 256) {
        int h = idx >> 7, c = idx & 127;
        s_wbT[idx] = w_b[c * 12 + h];
    }
    for (int idx = t; idx < 768; idx += 256)
        s_w[idx] = __expf(ss[(size_t)i * 768 + idx]) - 0.99f;
    if (t < 12) {
        float x = head_w[t];
        float sp = (x > 20.f) ? x : log1pf(__expf(x));
        s_hw[t] = sp * 0.13608276348795434f;   // sqrt(1/54)
        s_bb[t] = b_b[t];
        s_m[t] = -1e30f;
        s_s[t] = 0.f;
    }
    if (t == 0) s_maski = mask[i];
    __syncthreads();
    const float mask_i = s_maski;

    // mappings
    const int lc = (t & 31) * 4;   // z staging column
    const int jr = t >> 5;         // z staging row group
    const int hh = t & 3;          // logits: head group
    const int jq = t >> 2;         // logits: local j
    const int wrp = t >> 5, lane = t & 31;  // softmax
    const int cg = t >> 2, sl = t & 3;      // o_pair

    ull pacc[12][2];
    #pragma unroll
    for (int h = 0; h < 12; h++) { pacc[h][0] = 0ull; pacc[h][1] = 0ull; }

    for (int j0 = 0; j0 < 768; j0 += 64) {
        __syncthreads();   // protect s_z / s_p against previous tile's o_pair readers

        // ---- stage z tile ----
        #pragma unroll
        for (int r = 0; r < 8; r++) {
            int jj = jr + r * 8;
            float4 zv = *(const float4*)&z[((size_t)(i * 768 + j0 + jj)) * 128 + lc];
            *(float4*)&s_z[jj * 132 + lc] = zv;
        }
        __syncthreads();

        // ---- logits for this tile ----
        {
            const int j = j0 + jq;
            const float maskterm = 100000.f * (mask_i * mask[j] - 1.f);
            const float* zr = &s_z[jq * 132];

            ull b0[3] = {0ull, 0ull, 0ull}, b1[3] = {0ull, 0ull, 0ull};
            #pragma unroll 8
            for (int c = 0; c < 128; c += 4) {
                ulonglong2 zp = *(const ulonglong2*)&zr[c];
                #pragma unroll
                for (int q = 0; q < 3; q++) {
                    ulonglong2 wp = *(const ulonglong2*)&s_wbT[(hh + 4 * q) * 128 + c];
                    ffma2(b0[q], zp.x, wp.x);
                    ffma2(b1[q], zp.y, wp.y);
                }
            }
            #pragma unroll
            for (int q = 0; q < 3; q++) {
                const int h = hh + 4 * q;
                float2 u0 = unpack2(b0[q]), u1 = unpack2(b1[q]);
                float bias = ((u0.x + u0.y) + (u1.x + u1.y)) + s_bb[h];
                // qk
                float qk = 0.f;
                const float* kr = &g_k[(size_t)j * 192 + h * 16];
                const float* qr = &s_q[h * 16];
                #pragma unroll
                for (int c = 0; c < 16; c += 4) {
                    float4 kv = *(const float4*)&kr[c];
                    qk += qr[c] * kv.x + qr[c + 1] * kv.y + qr[c + 2] * kv.z + qr[c + 3] * kv.w;
                }
                // point distances (12 floats, 16B aligned)
                float pts = 0.f;
                const float4* kp = (const float4*)&g_kpts[(size_t)j * 144 + h * 12];
                const float4* qp = (const float4*)&s_qp[h * 12];
                #pragma unroll
                for (int e = 0; e < 3; e++) {
                    float4 kv = kp[e], qv = qp[e];
                    float d0 = qv.x - kv.x, d1 = qv.y - kv.y, d2 = qv.z - kv.z, d3 = qv.w - kv.w;
                    pts += d0 * d0 + d1 * d1 + d2 * d2 + d3 * d3;
                }
                s_logit[h * 768 + j] = qk * 0.14433756729740643f
                                     + 0.5773502691896258f * bias
                                     - 0.5f * s_hw[h] * pts
                                     + maskterm;
            }
        }
        __syncthreads();

        // ---- online softmax tile-update (warp per head) ----
        for (int h = wrp; h < 12; h += 8) {
            float l0 = s_logit[h * 768 + j0 + lane];
            float l1 = s_logit[h * 768 + j0 + lane + 32];
            float m_old = s_m[h];
            float mt = fmaxf(l0, l1);
            #pragma unroll
            for (int o = 16; o; o >>= 1) mt = fmaxf(mt, __shfl_xor_sync(0xffffffffu, mt, o));
            float m_new = fmaxf(m_old, mt);
            float p0 = __expf(l0 - m_new) * s_w[j0 + lane];
            float p1 = __expf(l1 - m_new) * s_w[j0 + lane + 32];
            s_p[h * 64 + lane] = p0;
            s_p[h * 64 + lane + 32] = p1;
            float sum = p0 + p1;
            #pragma unroll
            for (int o = 16; o; o >>= 1) sum += __shfl_xor_sync(0xffffffffu, sum, o);
            __syncwarp();
            if (lane == 0) {
                float f = __expf(m_old - m_new);
                s_scale[h] = f;
                s_m[h] = m_new;
                s_s[h] = s_s[h] * f + sum;
            }
        }
        __syncthreads();

        // ---- o_pair accumulate over tile (z still resident in smem) ----
        #pragma unroll
        for (int h = 0; h < 12; h++) {
            float fs = s_scale[h];
            ull fh = pack2(fs, fs);
            fmul2(pacc[h][0], fh);
            fmul2(pacc[h][1], fh);
        }
        #pragma unroll
        for (int k = 0; k < 8; k++) {
            int jj = sl * 2 + k * 8;
            float2 za = *(const float2*)&s_z[jj * 132 + cg * 2];
            float2 zb = *(const float2*)&s_z[(jj + 1) * 132 + cg * 2];
            ull p0 = pack2(za.x, zb.x);
            ull p1 = pack2(za.y, zb.y);
            #pragma unroll
            for (int h = 0; h < 12; h++) {
                ull ap = *(const ull*)&s_p[h * 64 + jj];   // {p_jj, p_jj+1}
                ffma2(pacc[h][0], ap, p0);
                ffma2(pacc[h][1], ap, p1);
            }
        }
    }

    __syncthreads();
    if (t < 12) s_inv[t] = 1.f / s_s[t];
    __syncthreads();

    // ---- o_pair reduce over sl and write ----
    #pragma unroll
    for (int h = 0; h < 12; h++) {
        ull v0 = pacc[h][0], v1 = pacc[h][1];
        v0 = fadd2(v0, __shfl_xor_sync(0xffffffffu, v0, 1));
        v0 = fadd2(v0, __shfl_xor_sync(0xffffffffu, v0, 2));
        v1 = fadd2(v1, __shfl_xor_sync(0xffffffffu, v1, 1));
        v1 = fadd2(v1, __shfl_xor_sync(0xffffffffu, v1, 2));
        if (sl == 0) {
            float2 a = unpack2(v0), b = unpack2(v1);
            float2 o;
            o.x = (a.x + a.y) * s_inv[h];
            o.y = (b.x + b.y) * s_inv[h];
            *(float2*)&g_feats[(size_t)i * FEAT_N + 576 + h * 128 + cg * 2] = o;
        }
    }

    // ---- final attention weights for ov kernel ----
    for (int idx = t; idx < 9216; idx += 256) {
        int h = idx / 768;
        int j = idx - h * 768;
        g_a[(size_t)i * 9216 + idx] =
            __expf(s_logit[idx] - s_m[h]) * s_w[j] * s_inv[h];
    }
}

// ---------------- ov: o = a@v, o_pt(global) = a@v_pts ----------------
// grid (12 i-tiles of 64, 12 heads), 256 threads, 2x5 register tile
__global__ __launch_bounds__(256) void ov_kernel()
{
    __shared__ float s_a[64 * 64];    // [row][jj]
    __shared__ float s_v[64 * 40];    // [jj][40]

    const int i0 = blockIdx.x * 64;
    const int h  = blockIdx.y;
    const int t = threadIdx.x;
    const int ig = t >> 3;    // 0..31 -> 2 rows
    const int og = t & 7;     // 0..7  -> 5 outputs

    float acc[2][5] = {};

    for (int j0 = 0; j0 < 768; j0 += 64) {
        #pragma unroll
        for (int it = 0; it < 4; it++) {
            int idx = t + it * 256;
            int row = idx >> 4, q = idx & 15;
            float4 av = *(const float4*)&g_a[((size_t)(i0 + row) * 12 + h) * 768 + j0 + q * 4];
            *(float4*)&s_a[row * 64 + q * 4] = av;
        }
        #pragma unroll
        for (int it = 0; it < 10; it++) {
            int idx = t + it * 256;
            int jj = idx / 40, e = idx - jj * 40;
            s_v[idx] = (e < 16) ? g_v[(j0 + jj) * 192 + h * 16 + e]
                                : g_vpts[(j0 + jj) * 288 + h * 24 + (e - 16)];
        }
        __syncthreads();
        #pragma unroll 4
        for (int jj = 0; jj < 64; jj++) {
            float a0 = s_a[(ig * 2 + 0) * 64 + jj];
            float a1 = s_a[(ig * 2 + 1) * 64 + jj];
            const float* vp = &s_v[jj * 40 + og * 5];
            #pragma unroll
            for (int u = 0; u < 5; u++) {
                float vv = vp[u];
                acc[0][u] += a0 * vv;
                acc[1][u] += a1 * vv;
            }
        }
        __syncthreads();
    }
    #pragma unroll
    for (int r = 0; r < 2; r++) {
        int n = i0 + ig * 2 + r;
        #pragma unroll
        for (int u = 0; u < 5; u++) {
            int e = og * 5 + u;
            if (e < 16) g_feats[(size_t)n * FEAT_N + h * 16 + e] = acc[r][u];
            else        g_optg[n * 288 + h * 24 + (e - 16)] = acc[r][u];
        }
    }
}

// ---------------- optfinal: inverse-rotate o_pt, norms ----------------
__global__ __launch_bounds__(96) void optfinal_kernel(
    const float* __restrict__ rot, const float* __restrict__ trans)
{
    const int n = blockIdx.x;
    const int hp = threadIdx.x;
    float r[9], tr[3];
    #pragma unroll
    for (int e = 0; e < 9; e++) r[e] = rot[n * 9 + e];
    tr[0] = trans[n * 3 + 0]; tr[1] = trans[n * 3 + 1]; tr[2] = trans[n * 3 + 2];

    float gx = g_optg[n * 288 + hp * 3 + 0] - tr[0];
    float gy = g_optg[n * 288 + hp * 3 + 1] - tr[1];
    float gz = g_optg[n * 288 + hp * 3 + 2] - tr[2];
    float l0 = r[0] * gx + r[3] * gy + r[6] * gz;
    float l1 = r[1] * gx + r[4] * gy + r[7] * gz;
    float l2 = r[2] * gx + r[5] * gy + r[8] * gz;

    float* f = &g_feats[(size_t)n * FEAT_N];
    f[192 + hp] = l0;
    f[288 + hp] = l1;
    f[384 + hp] = l2;
    f[480 + hp] = sqrtf(l0 * l0 + l1 * l1 + l2 * l2 + 1e-8f);
}

// ---------------- launch ----------------
extern "C" void kernel_launch(void* const* d_in, const int* in_sizes, int n_in,
                              void* d_out, int out_size)
{
    const float* s       = (const float*)d_in[0];
    const float* z       = (const float*)d_in[1];
    const float* rot     = (const float*)d_in[2];
    const float* trans   = (const float*)d_in[3];
    const float* mask    = (const float*)d_in[4];
    const float* ss      = (const float*)d_in[5];
    const float* w_q     = (const float*)d_in[6];
    const float* b_q     = (const float*)d_in[7];
    const float* w_kv    = (const float*)d_in[8];
    const float* b_kv    = (const float*)d_in[9];
    const float* w_qp    = (const float*)d_in[10];
    const float* b_qp    = (const float*)d_in[11];
    const float* w_kvp   = (const float*)d_in[12];
    const float* b_kvp   = (const float*)d_in[13];
    const float* w_b     = (const float*)d_in[14];
    const float* b_b     = (const float*)d_in[15];
    const float* head_w  = (const float*)d_in[16];
    const float* w_out   = (const float*)d_in[17];
    const float* b_out   = (const float*)d_in[18];
    float* out = (float*)d_out;

    float* proj;  cudaGetSymbolAddress((void**)&proj, g_proj);
    float* feats; cudaGetSymbolAddress((void**)&feats, g_feats);

    static bool attr_done = false;
    if (!attr_done) {
        cudaFuncSetAttribute(attn_kernel,
                             cudaFuncAttributeMaxDynamicSharedMemorySize,
                             ATTN_SMEM_FLOATS * 4);
        attr_done = true;
    }

    // K1: projections (768 x 1152)
    gemm_kernel<<<dim3(18, 24), 256>>>(
        s, CS, w_q, w_kv, w_qp, w_kvp, b_q, b_kv, b_qp, b_kvp,
        192, 576, 720, 1152, proj, PROJ_N);

    // K2: split k/v, rotate points
    prep_kernel<<<NN, 256>>>(rot, trans);

    // K3: fused logits + online softmax + o_pair (single z pass)
    attn_kernel<<<NN, 256, ATTN_SMEM_FLOATS * 4>>>(z, ss, mask, w_b, b_b, head_w);

    // K4: o and o_pt accumulation
    ov_kernel<<<dim3(12, 12), 256>>>();

    // K5: finalize o_pt + norms
    optfinal_kernel<<<NN, 96>>>(rot, trans);

    // K6: output GEMM (768 x 384, K=2112)
    gemm_kernel<<<dim3(6, 24), 256>>>(
        feats, FEAT_N, w_out, w_out, w_out, w_out, b_out, b_out, b_out, b_out,
        384, 384, 384, 384, out, CS);
}

// round 5
// speedup vs baseline: 1.6865x; 1.1211x over previous
#include <cuda_runtime.h>
#include <math.h>
#include <stdint.h>

// Problem constants
#define NN 768
#define HH 12
#define CC 16
#define CZ 128
#define CS 384
#define PROJ_N 1152
#define FEAT_N 2112   // [o 192 | ptx 96 | pty 96 | ptz 96 | ptnorm 96 | opair 1536]

typedef unsigned long long ull;

#define S1 0.14433756729740643f      // sqrt(1/48)
#define SQ13 0.5773502691896258f     // sqrt(1/3)
#define HWF 0.13608276348795434f     // sqrt(1/54)

// ---------------- f32x2 helpers ----------------
__device__ __forceinline__ void ffma2(ull& d, ull a, ull b) {
    asm("fma.rn.f32x2 %0, %1, %2, %0;" : "+l"(d) : "l"(a), "l"(b));
}
__device__ __forceinline__ void fmul2(ull& d, ull a) {
    asm("mul.rn.f32x2 %0, %0, %1;" : "+l"(d) : "l"(a));
}
__device__ __forceinline__ ull pack2(float x, float y) {
    ull r; asm("mov.b64 %0, {%1, %2};" : "=l"(r) : "f"(x), "f"(y)); return r;
}
__device__ __forceinline__ float2 unpack2(ull v) {
    float2 r; asm("mov.b64 {%0, %1}, %2;" : "=f"(r.x), "=f"(r.y) : "l"(v)); return r;
}
__device__ __forceinline__ void cpa16(uint32_t dst, const void* src) {
    asm volatile("cp.async.cg.shared.global [%0], [%1], 16;\n" :: "r"(dst), "l"(src));
}

// ---------------- scratch ----------------
__device__ float g_proj[NN * PROJ_N];
__device__ float g_v[NN * 192];
__device__ float g_vpts[NN * 288];            // [n][h*8+p][3]
__device__ float g_qb[HH * NN * 32];          // [h][i][32] logit-A rows
__device__ float g_kb[HH * NN * 32];          // [h][j][32] logit-B rows
__device__ float g_qkp[(size_t)NN * HH * NN]; // [i][h][j] qk+pts+mask logits
__device__ float g_a[(size_t)NN * HH * NN];   // [i][h][j] unnormalized p
__device__ float g_af[NN * HH * 12];          // [i][h][tile] rescale factors
__device__ float g_optg[NN * 288];
__device__ float g_feats[NN * FEAT_N];

// ---------------- GEMM: out = A @ W + bias, segmented over N ----------------
__global__ __launch_bounds__(256) void gemm_kernel(
    const float* __restrict__ A, int K,
    const float* __restrict__ w0, const float* __restrict__ w1,
    const float* __restrict__ w2, const float* __restrict__ w3,
    const float* __restrict__ b0, const float* __restrict__ b1,
    const float* __restrict__ b2, const float* __restrict__ b3,
    int e0, int e1, int e2, int e3,
    float* __restrict__ out, int ldo)
{
    __shared__ float As[16][34];
    __shared__ float Bs[16][64];

    const int m0 = blockIdx.y * 32;
    const int n0 = blockIdx.x * 64;
    const int t = threadIdx.x;

    const int bkr = t >> 4;
    const int n   = n0 + (t & 15) * 4;
    const float* W; const float* bias; int base, segN;
    if (n < e0)      { W = w0; bias = b0; base = 0;  segN = e0; }
    else if (n < e1) { W = w1; bias = b1; base = e0; segN = e1 - e0; }
    else if (n < e2) { W = w2; bias = b2; base = e1; segN = e2 - e1; }
    else             { W = w3; bias = b3; base = e2; segN = e3 - e2; }

    const int ar  = t >> 2;
    const int ac4 = (t & 3) * 4;
    const int ty  = t >> 4;
    const int tx  = t & 15;

    float acc[2][4] = {};

    for (int k0 = 0; k0 < K; k0 += 16) {
        if (t < 128) {
            float4 av = *(const float4*)&A[(size_t)(m0 + ar) * K + k0 + ac4];
            As[ac4 + 0][ar] = av.x; As[ac4 + 1][ar] = av.y;
            As[ac4 + 2][ar] = av.z; As[ac4 + 3][ar] = av.w;
        }
        float4 bv = *(const float4*)&W[(size_t)(k0 + bkr) * segN + (n - base)];
        *(float4*)&Bs[bkr][(t & 15) * 4] = bv;
        __syncthreads();
        #pragma unroll
        for (int kk = 0; kk < 16; kk++) {
            float2 a2 = *(const float2*)&As[kk][ty * 2];
            float4 b4 = *(const float4*)&Bs[kk][tx * 4];
            acc[0][0] += a2.x * b4.x; acc[0][1] += a2.x * b4.y;
            acc[0][2] += a2.x * b4.z; acc[0][3] += a2.x * b4.w;
            acc[1][0] += a2.y * b4.x; acc[1][1] += a2.y * b4.y;
            acc[1][2] += a2.y * b4.z; acc[1][3] += a2.y * b4.w;
        }
        __syncthreads();
    }
    float4 bb = *(const float4*)&bias[n - base];
    #pragma unroll
    for (int r = 0; r < 2; r++) {
        float4 o;
        o.x = acc[r][0] + bb.x; o.y = acc[r][1] + bb.y;
        o.z = acc[r][2] + bb.z; o.w = acc[r][3] + bb.w;
        *(float4*)&out[(size_t)(m0 + ty * 2 + r) * ldo + n] = o;
    }
}

// ---------------- prep: split k/v, rotate points, build logit-GEMM rows ----------------
__global__ __launch_bounds__(384) void prep_kernel(
    const float* __restrict__ rot, const float* __restrict__ trans,
    const float* __restrict__ head_w)
{
    __shared__ float s_qp3[144];   // rotated q_pts  [(h*4+p)*3+ii]
    __shared__ float s_kp3[144];   // rotated k_pts

    const int n = blockIdx.x;
    const int t = threadIdx.x;
    const float* pr = &g_proj[(size_t)n * PROJ_N];

    // k -> g_kb[0..15], v -> g_v
    if (t < 192) {
        int h = t >> 4, c = t & 15;
        g_kb[((size_t)h * NN + n) * 32 + c] = pr[192 + h * 32 + c];
        g_v[n * 192 + t] = pr[192 + h * 32 + 16 + c];
    }
    float r[9], tr[3];
    #pragma unroll
    for (int e = 0; e < 9; e++) r[e] = rot[n * 9 + e];
    tr[0] = trans[n * 3 + 0]; tr[1] = trans[n * 3 + 1]; tr[2] = trans[n * 3 + 2];

    if (t < 48) {  // q_pts
        float p0 = pr[576 + 0 * 48 + t];
        float p1 = pr[576 + 1 * 48 + t];
        float p2 = pr[576 + 2 * 48 + t];
        #pragma unroll
        for (int ii = 0; ii < 3; ii++)
            s_qp3[t * 3 + ii] = r[ii * 3 + 0] * p0 + r[ii * 3 + 1] * p1 + r[ii * 3 + 2] * p2 + tr[ii];
    }
    if (t >= 64 && t < 208) {  // kv_pts
        int u = t - 64;
        float p0 = pr[720 + 0 * 144 + u];
        float p1 = pr[720 + 1 * 144 + u];
        float p2 = pr[720 + 2 * 144 + u];
        int h = u / 12, p = u % 12;
        #pragma unroll
        for (int ii = 0; ii < 3; ii++) {
            float o = r[ii * 3 + 0] * p0 + r[ii * 3 + 1] * p1 + r[ii * 3 + 2] * p2 + tr[ii];
            if (p < 4) s_kp3[(h * 4 + p) * 3 + ii] = o;
            else       g_vpts[n * 288 + (h * 8 + (p - 4)) * 3 + ii] = o;
        }
    }
    __syncthreads();

    // build g_qb / g_kb[16..31]
    {
        int h = t >> 5, e = t & 31;
        float x = head_w[h];
        float hw = ((x > 20.f) ? x : log1pf(__expf(x))) * HWF;

        float qv;
        if (e < 16)       qv = pr[h * 16 + e] * S1;
        else if (e < 28)  qv = s_qp3[h * 12 + (e - 16)] * hw;
        else if (e == 28) qv = -0.5f * hw;
        else if (e == 29) {
            float nq = 0.f;
            #pragma unroll
            for (int d = 0; d < 12; d++) { float v = s_qp3[h * 12 + d]; nq += v * v; }
            qv = -0.5f * hw * nq;
        } else qv = 0.f;
        g_qb[((size_t)h * NN + n) * 32 + e] = qv;

        if (e >= 16) {
            float kv2;
            if (e < 28)       kv2 = s_kp3[h * 12 + (e - 16)];
            else if (e == 28) {
                float nk = 0.f;
                #pragma unroll
                for (int d = 0; d < 12; d++) { float v = s_kp3[h * 12 + d]; nk += v * v; }
                kv2 = nk;
            }
            else if (e == 29) kv2 = 1.f;
            else              kv2 = 0.f;
            g_kb[((size_t)h * NN + n) * 32 + e] = kv2;
        }
    }
}

// ---------------- qkpts: g_qkp[i][h][j] = qk*s1 + pts-term + maskterm ----------------
// 30-dim GEMM per head; grid (12 i-tiles, 12 j-tiles, 12 heads)
// Identity used: -0.5*hw*|qp-kp|^2 = (hw*qp)·kp + (-0.5*hw)*|kp|^2 + (-0.5*hw*|qp|^2)*1
__global__ __launch_bounds__(256) void qkpts_kernel(const float* __restrict__ mask)
{
    __shared__ float As[32][68];   // [k][i]
    __shared__ float Bs[32][68];   // [k][j]
    __shared__ float s_mi[64], s_mj[64];

    const int i0 = blockIdx.x * 64;
    const int j0 = blockIdx.y * 64;
    const int h  = blockIdx.z;
    const int t = threadIdx.x;

    #pragma unroll
    for (int r2 = 0; r2 < 2; r2++) {
        int li = t + r2 * 256;
        int row = li >> 3, c4 = (li & 7) * 4;
        float4 a = *(const float4*)&g_qb[((size_t)h * NN + i0 + row) * 32 + c4];
        As[c4 + 0][row] = a.x; As[c4 + 1][row] = a.y;
        As[c4 + 2][row] = a.z; As[c4 + 3][row] = a.w;
        float4 b = *(const float4*)&g_kb[((size_t)h * NN + j0 + row) * 32 + c4];
        Bs[c4 + 0][row] = b.x; Bs[c4 + 1][row] = b.y;
        Bs[c4 + 2][row] = b.z; Bs[c4 + 3][row] = b.w;
    }
    if (t < 64)              s_mi[t] = mask[i0 + t];
    else if (t < 128)        s_mj[t - 64] = mask[j0 + t - 64];
    __syncthreads();

    const int ty = t >> 4, tx = t & 15;
    float acc[4][4] = {};
    #pragma unroll
    for (int k = 0; k < 32; k++) {
        float4 a4 = *(const float4*)&As[k][ty * 4];
        float4 b4 = *(const float4*)&Bs[k][tx * 4];
        acc[0][0] += a4.x * b4.x; acc[0][1] += a4.x * b4.y; acc[0][2] += a4.x * b4.z; acc[0][3] += a4.x * b4.w;
        acc[1][0] += a4.y * b4.x; acc[1][1] += a4.y * b4.y; acc[1][2] += a4.y * b4.z; acc[1][3] += a4.y * b4.w;
        acc[2][0] += a4.z * b4.x; acc[2][1] += a4.z * b4.y; acc[2][2] += a4.z * b4.z; acc[2][3] += a4.z * b4.w;
        acc[3][0] += a4.w * b4.x; acc[3][1] += a4.w * b4.y; acc[3][2] += a4.w * b4.z; acc[3][3] += a4.w * b4.w;
    }
    #pragma unroll
    for (int rr = 0; rr < 4; rr++) {
        float mi = s_mi[ty * 4 + rr];
        float4 o;
        o.x = acc[rr][0] + 100000.f * (mi * s_mj[tx * 4 + 0] - 1.f);
        o.y = acc[rr][1] + 100000.f * (mi * s_mj[tx * 4 + 1] - 1.f);
        o.z = acc[rr][2] + 100000.f * (mi * s_mj[tx * 4 + 2] - 1.f);
        o.w = acc[rr][3] + 100000.f * (mi * s_mj[tx * 4 + 3] - 1.f);
        *(float4*)&g_qkp[(size_t)(i0 + ty * 4 + rr) * 9216 + h * 768 + j0 + tx * 4] = o;
    }
}

// ---------------- attn: bias + online softmax + o_pair, one z pass ----------------
#define AT_Z 8448   // 64 rows x 132 floats
#define ATTN_SMEM_FLOATS (2 * AT_Z + 768 + 768 + 1536 + 144)

__global__ __launch_bounds__(256, 2) void attn_kernel(
    const float* __restrict__ z, const float* __restrict__ ss,
    const float* __restrict__ w_b, const float* __restrict__ b_b)
{
    extern __shared__ float sm[];
    float* s_z   = sm;                  // [2][64][132]
    float* s_lp  = sm + 2 * AT_Z;       // [12][64] raw logits then probs
    float* s_w   = s_lp + 768;          // exp(ss)-0.99
    float* s_wbT = s_w + 768;           // [h][c]
    float* s_mh  = s_wbT + 1536;        // [h][tile] running max history
    __shared__ float s_m[12], s_s[12], s_scale[12], s_inv[12], s_bb[12];

    const int i = blockIdx.x;
    const int t = threadIdx.x;

    const int lc = (t & 31) * 4;
    const int jr = t >> 5;
    const uint32_t zbase = (uint32_t)__cvta_generic_to_shared(s_z);

    // prologue: stage tile 0 into buffer 0
    {
        const float* src = z + ((size_t)(i * 768 + jr)) * 128 + lc;
        #pragma unroll
        for (int r = 0; r < 8; r++)
            cpa16(zbase + (uint32_t)(((jr + r * 8) * 132 + lc) * 4), src + (size_t)r * 8 * 128);
        asm volatile("cp.async.commit_group;\n" ::);
    }

    for (int idx = t; idx < 1536; idx += 256) {
        int h = idx >> 7, c = idx & 127;
        s_wbT[idx] = w_b[c * 12 + h];
    }
    for (int idx = t; idx < 768; idx += 256)
        s_w[idx] = __expf(ss[(size_t)i * 768 + idx]) - 0.99f;
    if (t < 12) {
        s_bb[t] = b_b[t];
        s_m[t] = -1e30f;
        s_s[t] = 0.f;
    }
    __syncthreads();

    const int hh = t & 3, jq = t >> 2;           // logits mapping
    const int wrp = t >> 5, lane = t & 31;       // softmax mapping
    const int hg = t >> 6, cp = t & 63;          // o_pair mapping

    ull acc[3][2] = {};

    for (int tt = 0; tt < 12; tt++) {
        const int cur = tt & 1;
        if (tt < 11) {
            const float* src = z + ((size_t)(i * 768 + (tt + 1) * 64 + jr)) * 128 + lc;
            const uint32_t dbase = zbase + (uint32_t)(((cur ^ 1) * AT_Z) * 4);
            #pragma unroll
            for (int r = 0; r < 8; r++)
                cpa16(dbase + (uint32_t)(((jr + r * 8) * 132 + lc) * 4), src + (size_t)r * 8 * 128);
            asm volatile("cp.async.commit_group;\n" ::);
            asm volatile("cp.async.wait_group 1;\n" ::);
        } else {
            asm volatile("cp.async.wait_group 0;\n" ::);
        }
        __syncthreads();

        // ---- logits: qkpts base + z-bias ----
        {
            const float* zr = s_z + cur * AT_Z + jq * 132;
            ull b0[3] = {0ull, 0ull, 0ull}, b1[3] = {0ull, 0ull, 0ull};
            #pragma unroll 4
            for (int c = 0; c < 128; c += 4) {
                ulonglong2 zp = *(const ulonglong2*)&zr[c];
                #pragma unroll
                for (int q = 0; q < 3; q++) {
                    ulonglong2 wp = *(const ulonglong2*)&s_wbT[(hh + 4 * q) * 128 + c];
                    ffma2(b0[q], zp.x, wp.x);
                    ffma2(b1[q], zp.y, wp.y);
                }
            }
            #pragma unroll
            for (int q = 0; q < 3; q++) {
                const int h = hh + 4 * q;
                float2 u0 = unpack2(b0[q]), u1 = unpack2(b1[q]);
                float bias = ((u0.x + u0.y) + (u1.x + u1.y)) + s_bb[h];
                float base = g_qkp[(size_t)i * 9216 + h * 768 + tt * 64 + jq];
                s_lp[h * 64 + jq] = base + SQ13 * bias;
            }
        }
        __syncthreads();

        // ---- online softmax (warp per head) ----
        for (int h = wrp; h < 12; h += 8) {
            float l0 = s_lp[h * 64 + lane];
            float l1 = s_lp[h * 64 + lane + 32];
            float m_old = s_m[h];
            float mt = fmaxf(l0, l1);
            #pragma unroll
            for (int o = 16; o; o >>= 1) mt = fmaxf(mt, __shfl_xor_sync(0xffffffffu, mt, o));
            float m_new = fmaxf(m_old, mt);
            float p0 = __expf(l0 - m_new) * s_w[tt * 64 + lane];
            float p1 = __expf(l1 - m_new) * s_w[tt * 64 + lane + 32];
            s_lp[h * 64 + lane] = p0;
            s_lp[h * 64 + lane + 32] = p1;
            g_a[(size_t)i * 9216 + h * 768 + tt * 64 + lane] = p0;
            g_a[(size_t)i * 9216 + h * 768 + tt * 64 + lane + 32] = p1;
            float sum = p0 + p1;
            #pragma unroll
            for (int o = 16; o; o >>= 1) sum += __shfl_xor_sync(0xffffffffu, sum, o);
            __syncwarp();
            if (lane == 0) {
                float f = __expf(m_old - m_new);
                s_scale[h] = f;
                s_m[h] = m_new;
                s_s[h] = s_s[h] * f + sum;
                s_mh[h * 12 + tt] = m_new;
            }
        }
        __syncthreads();

        // ---- o_pair accumulate: thread owns 3 heads x 2 cols, all jj ----
        {
            #pragma unroll
            for (int q = 0; q < 3; q++) {
                float f = s_scale[hg * 3 + q];
                ull ff = pack2(f, f);
                fmul2(acc[q][0], ff);
                fmul2(acc[q][1], ff);
            }
            const float* zb = s_z + cur * AT_Z + 2 * cp;
            #pragma unroll 4
            for (int jp = 0; jp < 32; jp++) {
                int jj = jp * 2;
                float2 z0 = *(const float2*)&zb[jj * 132];
                float2 z1 = *(const float2*)&zb[(jj + 1) * 132];
                ull zA = pack2(z0.x, z1.x);
                ull zB = pack2(z0.y, z1.y);
                #pragma unroll
                for (int q = 0; q < 3; q++) {
                    ull ap = *(const ull*)&s_lp[(hg * 3 + q) * 64 + jj];
                    ffma2(acc[q][0], ap, zA);
                    ffma2(acc[q][1], ap, zB);
                }
            }
        }
        __syncthreads();   // buffer cur reused for tile tt+2 next iteration
    }

    if (t < 12) s_inv[t] = 1.f / s_s[t];
    __syncthreads();

    // per-(h,tile) rescale factors for ov
    if (t < 144) {
        int h = t / 12;
        g_af[(size_t)i * 144 + t] = __expf(s_mh[t] - s_m[h]) * s_inv[h];
    }

    // o_pair write
    #pragma unroll
    for (int q = 0; q < 3; q++) {
        int h = hg * 3 + q;
        float inv = s_inv[h];
        float2 uA = unpack2(acc[q][0]), uB = unpack2(acc[q][1]);
        float2 o;
        o.x = (uA.x + uA.y) * inv;
        o.y = (uB.x + uB.y) * inv;
        *(float2*)&g_feats[(size_t)i * FEAT_N + 576 + h * 128 + 2 * cp] = o;
    }
}

// ---------------- ov: o = a@v, o_pt(global) = a@v_pts (applies g_af rescale) ----------------
__global__ __launch_bounds__(256) void ov_kernel()
{
    __shared__ float s_a[64 * 64];
    __shared__ float s_v[64 * 40];

    const int i0 = blockIdx.x * 64;
    const int h  = blockIdx.y;
    const int t = threadIdx.x;
    const int ig = t >> 3;
    const int og = t & 7;

    float acc[2][5] = {};

    for (int j0 = 0; j0 < 768; j0 += 64) {
        const int tile = j0 >> 6;
        #pragma unroll
        for (int it = 0; it < 4; it++) {
            int idx = t + it * 256;
            int row = idx >> 4, q = idx & 15;
            float f = g_af[(size_t)(i0 + row) * 144 + h * 12 + tile];
            float4 av = *(const float4*)&g_a[((size_t)(i0 + row) * 12 + h) * 768 + j0 + q * 4];
            av.x *= f; av.y *= f; av.z *= f; av.w *= f;
            *(float4*)&s_a[row * 64 + q * 4] = av;
        }
        #pragma unroll
        for (int it = 0; it < 10; it++) {
            int idx = t + it * 256;
            int jj = idx / 40, e = idx - jj * 40;
            s_v[idx] = (e < 16) ? g_v[(j0 + jj) * 192 + h * 16 + e]
                                : g_vpts[(j0 + jj) * 288 + h * 24 + (e - 16)];
        }
        __syncthreads();
        #pragma unroll 4
        for (int jj = 0; jj < 64; jj++) {
            float a0 = s_a[(ig * 2 + 0) * 64 + jj];
            float a1 = s_a[(ig * 2 + 1) * 64 + jj];
            const float* vp = &s_v[jj * 40 + og * 5];
            #pragma unroll
            for (int u = 0; u < 5; u++) {
                float vv = vp[u];
                acc[0][u] += a0 * vv;
                acc[1][u] += a1 * vv;
            }
        }
        __syncthreads();
    }
    #pragma unroll
    for (int r = 0; r < 2; r++) {
        int n = i0 + ig * 2 + r;
        #pragma unroll
        for (int u = 0; u < 5; u++) {
            int e = og * 5 + u;
            if (e < 16) g_feats[(size_t)n * FEAT_N + h * 16 + e] = acc[r][u];
            else        g_optg[n * 288 + h * 24 + (e - 16)] = acc[r][u];
        }
    }
}

// ---------------- optfinal ----------------
__global__ __launch_bounds__(96) void optfinal_kernel(
    const float* __restrict__ rot, const float* __restrict__ trans)
{
    const int n = blockIdx.x;
    const int hp = threadIdx.x;
    float r[9], tr[3];
    #pragma unroll
    for (int e = 0; e < 9; e++) r[e] = rot[n * 9 + e];
    tr[0] = trans[n * 3 + 0]; tr[1] = trans[n * 3 + 1]; tr[2] = trans[n * 3 + 2];

    float gx = g_optg[n * 288 + hp * 3 + 0] - tr[0];
    float gy = g_optg[n * 288 + hp * 3 + 1] - tr[1];
    float gz = g_optg[n * 288 + hp * 3 + 2] - tr[2];
    float l0 = r[0] * gx + r[3] * gy + r[6] * gz;
    float l1 = r[1] * gx + r[4] * gy + r[7] * gz;
    float l2 = r[2] * gx + r[5] * gy + r[8] * gz;

    float* f = &g_feats[(size_t)n * FEAT_N];
    f[192 + hp] = l0;
    f[288 + hp] = l1;
    f[384 + hp] = l2;
    f[480 + hp] = sqrtf(l0 * l0 + l1 * l1 + l2 * l2 + 1e-8f);
}

// ---------------- launch ----------------
extern "C" void kernel_launch(void* const* d_in, const int* in_sizes, int n_in,
                              void* d_out, int out_size)
{
    const float* s       = (const float*)d_in[0];
    const float* z       = (const float*)d_in[1];
    const float* rot     = (const float*)d_in[2];
    const float* trans   = (const float*)d_in[3];
    const float* mask    = (const float*)d_in[4];
    const float* ss      = (const float*)d_in[5];
    const float* w_q     = (const float*)d_in[6];
    const float* b_q     = (const float*)d_in[7];
    const float* w_kv    = (const float*)d_in[8];
    const float* b_kv    = (const float*)d_in[9];
    const float* w_qp    = (const float*)d_in[10];
    const float* b_qp    = (const float*)d_in[11];
    const float* w_kvp   = (const float*)d_in[12];
    const float* b_kvp   = (const float*)d_in[13];
    const float* w_b     = (const float*)d_in[14];
    const float* b_b     = (const float*)d_in[15];
    const float* head_w  = (const float*)d_in[16];
    const float* w_out   = (const float*)d_in[17];
    const float* b_out   = (const float*)d_in[18];
    float* out = (float*)d_out;

    float* proj;  cudaGetSymbolAddress((void**)&proj, g_proj);
    float* feats; cudaGetSymbolAddress((void**)&feats, g_feats);

    static bool attr_done = false;
    if (!attr_done) {
        cudaFuncSetAttribute(attn_kernel,
                             cudaFuncAttributeMaxDynamicSharedMemorySize,
                             ATTN_SMEM_FLOATS * 4);
        attr_done = true;
    }

    // K1: projections (768 x 1152)
    gemm_kernel<<<dim3(18, 24), 256>>>(
        s, CS, w_q, w_kv, w_qp, w_kvp, b_q, b_kv, b_qp, b_kvp,
        192, 576, 720, 1152, proj, PROJ_N);

    // K2: split k/v, rotate points, build logit-GEMM rows
    prep_kernel<<<NN, 384>>>(rot, trans, head_w);

    // K2b: qk+pts+mask logits as 30-dim GEMM
    qkpts_kernel<<<dim3(12, 12, 12), 256>>>(mask);

    // K3: fused bias + online softmax + o_pair (single z pass)
    attn_kernel<<<NN, 256, ATTN_SMEM_FLOATS * 4>>>(z, ss, w_b, b_b);

    // K4: o and o_pt accumulation (applies rescale factors)
    ov_kernel<<<dim3(12, 12), 256>>>();

    // K5: finalize o_pt + norms
    optfinal_kernel<<<NN, 96>>>(rot, trans);

    // K6: output GEMM (768 x 384, K=2112)
    gemm_kernel<<<dim3(6, 24), 256>>>(
        feats, FEAT_N, w_out, w_out, w_out, w_out, b_out, b_out, b_out, b_out,
        384, 384, 384, 384, out, CS);
}

// round 6
// speedup vs baseline: 2.4568x; 1.4567x over previous
#include <cuda_runtime.h>
#include <math.h>
#include <stdint.h>

// Problem constants
#define NN 768
#define HH 12
#define CC 16
#define CZ 128
#define CS 384
#define PROJ_N 1152
#define FEAT_N 2112   // [o 192 | ptx 96 | pty 96 | ptz 96 | ptnorm 96 | opair 1536]

typedef unsigned long long ull;

#define S1 0.14433756729740643f      // sqrt(1/48)
#define SQ13 0.5773502691896258f     // sqrt(1/3)
#define HWF 0.13608276348795434f     // sqrt(1/54)

// ---------------- f32x2 helpers ----------------
__device__ __forceinline__ void ffma2(ull& d, ull a, ull b) {
    asm("fma.rn.f32x2 %0, %1, %2, %0;" : "+l"(d) : "l"(a), "l"(b));
}
__device__ __forceinline__ ull pack2(float x, float y) {
    ull r; asm("mov.b64 %0, {%1, %2};" : "=l"(r) : "f"(x), "f"(y)); return r;
}
__device__ __forceinline__ float2 unpack2(ull v) {
    float2 r; asm("mov.b64 {%0, %1}, %2;" : "=f"(r.x), "=f"(r.y) : "l"(v)); return r;
}

// ---------------- scratch ----------------
__device__ float g_proj[NN * PROJ_N];
__device__ float g_v[NN * 192];
__device__ float g_vpts[NN * 288];            // [n][h*8+p][3]
__device__ float g_qb[HH * NN * 32];          // [h][i][32] logit-A rows
__device__ float g_kb[HH * NN * 32];          // [h][j][32] logit-B rows
__device__ float g_qkp[(size_t)NN * HH * NN]; // [i][h][j] qk+pts+mask logits
__device__ float g_a[(size_t)NN * HH * NN];   // [i][h][j] normalized probs
__device__ float g_aT[(size_t)NN * NN * HH];  // [i][j][h] normalized probs
__device__ float g_optg[NN * 288];
__device__ float g_feats[NN * FEAT_N];

// ---------------- GEMM: out = A @ W + bias, segmented over N ----------------
__global__ __launch_bounds__(256) void gemm_kernel(
    const float* __restrict__ A, int K,
    const float* __restrict__ w0, const float* __restrict__ w1,
    const float* __restrict__ w2, const float* __restrict__ w3,
    const float* __restrict__ b0, const float* __restrict__ b1,
    const float* __restrict__ b2, const float* __restrict__ b3,
    int e0, int e1, int e2, int e3,
    float* __restrict__ out, int ldo)
{
    __shared__ float As[16][34];
    __shared__ float Bs[16][64];

    const int m0 = blockIdx.y * 32;
    const int n0 = blockIdx.x * 64;
    const int t = threadIdx.x;

    const int bkr = t >> 4;
    const int n   = n0 + (t & 15) * 4;
    const float* W; const float* bias; int base, segN;
    if (n < e0)      { W = w0; bias = b0; base = 0;  segN = e0; }
    else if (n < e1) { W = w1; bias = b1; base = e0; segN = e1 - e0; }
    else if (n < e2) { W = w2; bias = b2; base = e1; segN = e2 - e1; }
    else             { W = w3; bias = b3; base = e2; segN = e3 - e2; }

    const int ar  = t >> 2;
    const int ac4 = (t & 3) * 4;
    const int ty  = t >> 4;
    const int tx  = t & 15;

    float acc[2][4] = {};

    for (int k0 = 0; k0 < K; k0 += 16) {
        if (t < 128) {
            float4 av = *(const float4*)&A[(size_t)(m0 + ar) * K + k0 + ac4];
            As[ac4 + 0][ar] = av.x; As[ac4 + 1][ar] = av.y;
            As[ac4 + 2][ar] = av.z; As[ac4 + 3][ar] = av.w;
        }
        float4 bv = *(const float4*)&W[(size_t)(k0 + bkr) * segN + (n - base)];
        *(float4*)&Bs[bkr][(t & 15) * 4] = bv;
        __syncthreads();
        #pragma unroll
        for (int kk = 0; kk < 16; kk++) {
            float2 a2 = *(const float2*)&As[kk][ty * 2];
            float4 b4 = *(const float4*)&Bs[kk][tx * 4];
            acc[0][0] += a2.x * b4.x; acc[0][1] += a2.x * b4.y;
            acc[0][2] += a2.x * b4.z; acc[0][3] += a2.x * b4.w;
            acc[1][0] += a2.y * b4.x; acc[1][1] += a2.y * b4.y;
            acc[1][2] += a2.y * b4.z; acc[1][3] += a2.y * b4.w;
        }
        __syncthreads();
    }
    float4 bb = *(const float4*)&bias[n - base];
    #pragma unroll
    for (int r = 0; r < 2; r++) {
        float4 o;
        o.x = acc[r][0] + bb.x; o.y = acc[r][1] + bb.y;
        o.z = acc[r][2] + bb.z; o.w = acc[r][3] + bb.w;
        *(float4*)&out[(size_t)(m0 + ty * 2 + r) * ldo + n] = o;
    }
}

// ---------------- prep: split k/v, rotate points, build logit-GEMM rows ----------------
__global__ __launch_bounds__(384) void prep_kernel(
    const float* __restrict__ rot, const float* __restrict__ trans,
    const float* __restrict__ head_w)
{
    __shared__ float s_qp3[144];   // rotated q_pts  [(h*4+p)*3+ii]
    __shared__ float s_kp3[144];   // rotated k_pts

    const int n = blockIdx.x;
    const int t = threadIdx.x;
    const float* pr = &g_proj[(size_t)n * PROJ_N];

    if (t < 192) {
        int h = t >> 4, c = t & 15;
        g_kb[((size_t)h * NN + n) * 32 + c] = pr[192 + h * 32 + c];
        g_v[n * 192 + t] = pr[192 + h * 32 + 16 + c];
    }
    float r[9], tr[3];
    #pragma unroll
    for (int e = 0; e < 9; e++) r[e] = rot[n * 9 + e];
    tr[0] = trans[n * 3 + 0]; tr[1] = trans[n * 3 + 1]; tr[2] = trans[n * 3 + 2];

    if (t < 48) {
        float p0 = pr[576 + 0 * 48 + t];
        float p1 = pr[576 + 1 * 48 + t];
        float p2 = pr[576 + 2 * 48 + t];
        #pragma unroll
        for (int ii = 0; ii < 3; ii++)
            s_qp3[t * 3 + ii] = r[ii * 3 + 0] * p0 + r[ii * 3 + 1] * p1 + r[ii * 3 + 2] * p2 + tr[ii];
    }
    if (t >= 64 && t < 208) {
        int u = t - 64;
        float p0 = pr[720 + 0 * 144 + u];
        float p1 = pr[720 + 1 * 144 + u];
        float p2 = pr[720 + 2 * 144 + u];
        int h = u / 12, p = u % 12;
        #pragma unroll
        for (int ii = 0; ii < 3; ii++) {
            float o = r[ii * 3 + 0] * p0 + r[ii * 3 + 1] * p1 + r[ii * 3 + 2] * p2 + tr[ii];
            if (p < 4) s_kp3[(h * 4 + p) * 3 + ii] = o;
            else       g_vpts[n * 288 + (h * 8 + (p - 4)) * 3 + ii] = o;
        }
    }
    __syncthreads();

    {
        int h = t >> 5, e = t & 31;
        float x = head_w[h];
        float hw = ((x > 20.f) ? x : log1pf(__expf(x))) * HWF;

        float qv;
        if (e < 16)       qv = pr[h * 16 + e] * S1;
        else if (e < 28)  qv = s_qp3[h * 12 + (e - 16)] * hw;
        else if (e == 28) qv = -0.5f * hw;
        else if (e == 29) {
            float nq = 0.f;
            #pragma unroll
            for (int d = 0; d < 12; d++) { float v = s_qp3[h * 12 + d]; nq += v * v; }
            qv = -0.5f * hw * nq;
        } else qv = 0.f;
        g_qb[((size_t)h * NN + n) * 32 + e] = qv;

        if (e >= 16) {
            float kv2;
            if (e < 28)       kv2 = s_kp3[h * 12 + (e - 16)];
            else if (e == 28) {
                float nk = 0.f;
                #pragma unroll
                for (int d = 0; d < 12; d++) { float v = s_kp3[h * 12 + d]; nk += v * v; }
                kv2 = nk;
            }
            else if (e == 29) kv2 = 1.f;
            else              kv2 = 0.f;
            g_kb[((size_t)h * NN + n) * 32 + e] = kv2;
        }
    }
}

// ---------------- qkpts: g_qkp[i][h][j] = qk*s1 + pts-term + maskterm ----------------
__global__ __launch_bounds__(256) void qkpts_kernel(const float* __restrict__ mask)
{
    __shared__ float As[32][68];
    __shared__ float Bs[32][68];
    __shared__ float s_mi[64], s_mj[64];

    const int i0 = blockIdx.x * 64;
    const int j0 = blockIdx.y * 64;
    const int h  = blockIdx.z;
    const int t = threadIdx.x;

    #pragma unroll
    for (int r2 = 0; r2 < 2; r2++) {
        int li = t + r2 * 256;
        int row = li >> 3, c4 = (li & 7) * 4;
        float4 a = *(const float4*)&g_qb[((size_t)h * NN + i0 + row) * 32 + c4];
        As[c4 + 0][row] = a.x; As[c4 + 1][row] = a.y;
        As[c4 + 2][row] = a.z; As[c4 + 3][row] = a.w;
        float4 b = *(const float4*)&g_kb[((size_t)h * NN + j0 + row) * 32 + c4];
        Bs[c4 + 0][row] = b.x; Bs[c4 + 1][row] = b.y;
        Bs[c4 + 2][row] = b.z; Bs[c4 + 3][row] = b.w;
    }
    if (t < 64)              s_mi[t] = mask[i0 + t];
    else if (t < 128)        s_mj[t - 64] = mask[j0 + t - 64];
    __syncthreads();

    const int ty = t >> 4, tx = t & 15;
    float acc[4][4] = {};
    #pragma unroll
    for (int k = 0; k < 32; k++) {
        float4 a4 = *(const float4*)&As[k][ty * 4];
        float4 b4 = *(const float4*)&Bs[k][tx * 4];
        acc[0][0] += a4.x * b4.x; acc[0][1] += a4.x * b4.y; acc[0][2] += a4.x * b4.z; acc[0][3] += a4.x * b4.w;
        acc[1][0] += a4.y * b4.x; acc[1][1] += a4.y * b4.y; acc[1][2] += a4.y * b4.z; acc[1][3] += a4.y * b4.w;
        acc[2][0] += a4.z * b4.x; acc[2][1] += a4.z * b4.y; acc[2][2] += a4.z * b4.z; acc[2][3] += a4.z * b4.w;
        acc[3][0] += a4.w * b4.x; acc[3][1] += a4.w * b4.y; acc[3][2] += a4.w * b4.z; acc[3][3] += a4.w * b4.w;
    }
    #pragma unroll
    for (int rr = 0; rr < 4; rr++) {
        float mi = s_mi[ty * 4 + rr];
        float4 o;
        o.x = acc[rr][0] + 100000.f * (mi * s_mj[tx * 4 + 0] - 1.f);
        o.y = acc[rr][1] + 100000.f * (mi * s_mj[tx * 4 + 1] - 1.f);
        o.z = acc[rr][2] + 100000.f * (mi * s_mj[tx * 4 + 2] - 1.f);
        o.w = acc[rr][3] + 100000.f * (mi * s_mj[tx * 4 + 3] - 1.f);
        *(float4*)&g_qkp[(size_t)(i0 + ty * 4 + rr) * 9216 + h * 768 + j0 + tx * 4] = o;
    }
}

// ---------------- biassoftmax: logits = qkp + SQ13*(z@w_b + b_b); softmax; write a ----------------
// z rows read DIRECTLY from global (per-thread LDG.128, L1-friendly). No z in smem.
#define LPITCH 772
__global__ __launch_bounds__(256) void biassoftmax_kernel(
    const float* __restrict__ z, const float* __restrict__ ss,
    const float* __restrict__ w_b, const float* __restrict__ b_b)
{
    __shared__ float s_wbT[12 * 132];      // [h][c] padded: h-stride 132 -> conflict-free
    __shared__ float s_l[12 * LPITCH];     // logits then probs, pitch 772 (bank stride 1 per h)
    __shared__ float s_w[768];             // exp(ss)-0.99

    const int i = blockIdx.x;
    const int t = threadIdx.x;

    for (int idx = t; idx < 1536; idx += 256) {
        int h = idx / 128, c = idx - h * 128;
        s_wbT[h * 132 + c] = w_b[c * 12 + h];
    }
    for (int idx = t; idx < 768; idx += 256)
        s_w[idx] = __expf(ss[(size_t)i * 768 + idx]) - 0.99f;
    __syncthreads();

    const int hh = t & 3, r = t >> 2;   // thread: j-row r (0..63 per tile), heads hh,hh+4,hh+8

    float bb[3];
    #pragma unroll
    for (int q = 0; q < 3; q++) bb[q] = b_b[hh + 4 * q];

    for (int j0 = 0; j0 < 768; j0 += 64) {
        const int j = j0 + r;
        const float* zr = z + ((size_t)i * 768 + j) * 128;
        ull acc[3] = {0ull, 0ull, 0ull};
        #pragma unroll 4
        for (int c = 0; c < 128; c += 4) {
            float4 zv = __ldg((const float4*)(zr + c));
            ull z01 = pack2(zv.x, zv.y);
            ull z23 = pack2(zv.z, zv.w);
            #pragma unroll
            for (int q = 0; q < 3; q++) {
                float4 wv = *(const float4*)&s_wbT[(hh + 4 * q) * 132 + c];
                ffma2(acc[q], z01, pack2(wv.x, wv.y));
                ffma2(acc[q], z23, pack2(wv.z, wv.w));
            }
        }
        #pragma unroll
        for (int q = 0; q < 3; q++) {
            int h = hh + 4 * q;
            float2 u = unpack2(acc[q]);
            float base = g_qkp[((size_t)i * 12 + h) * 768 + j];
            s_l[h * LPITCH + j] = base + SQ13 * (u.x + u.y + bb[q]);
        }
    }
    __syncthreads();

    // softmax per head (warp per head)
    const int wrp = t >> 5, lane = t & 31;
    for (int h = wrp; h < 12; h += 8) {
        float* lr = &s_l[h * LPITCH];
        float m = -1e30f;
        for (int j = lane; j < 768; j += 32) m = fmaxf(m, lr[j]);
        #pragma unroll
        for (int o = 16; o; o >>= 1) m = fmaxf(m, __shfl_xor_sync(0xffffffffu, m, o));
        float sum = 0.f;
        for (int j = lane; j < 768; j += 32) {
            float p = __expf(lr[j] - m) * s_w[j];
            lr[j] = p;
            sum += p;
        }
        #pragma unroll
        for (int o = 16; o; o >>= 1) sum += __shfl_xor_sync(0xffffffffu, sum, o);
        float inv = 1.f / sum;
        for (int j = lane; j < 768; j += 32) lr[j] *= inv;
    }
    __syncthreads();

    // write [h][j] (for ov) and [j][h] (for opair)
    for (int idx = t; idx < 9216; idx += 256) {
        int h = idx / 768, j = idx - h * 768;
        g_a[(size_t)i * 9216 + idx] = s_l[h * LPITCH + j];
    }
    for (int idx = t; idx < 9216; idx += 256) {
        int j = idx / 12, h = idx - j * 12;
        g_aT[(size_t)i * 9216 + idx] = s_l[h * LPITCH + j];
    }
}

// ---------------- opair: o_pair[i][h][c] = sum_j a[i][j][h] * z[i][j][c] ----------------
// Block = one i, 4 warps. z rows read once, coalesced LDG.128 (lane = c/4). a staged in smem.
#define OP_SMEM_FLOATS (9216 + 4 * 12 * 128)
__global__ __launch_bounds__(128) void opair_kernel(const float* __restrict__ z)
{
    extern __shared__ float smop[];
    float* s_a    = smop;          // [j][12]
    float* s_part = smop + 9216;   // [w][12][128]

    const int i = blockIdx.x;
    const int t = threadIdx.x;
    const int w = t >> 5, lane = t & 31;

    for (int idx = t; idx < 2304; idx += 128)
        *(float4*)&s_a[idx * 4] = *(const float4*)&g_aT[(size_t)i * 9216 + idx * 4];
    __syncthreads();

    ull acc[12][2];
    #pragma unroll
    for (int h = 0; h < 12; h++) { acc[h][0] = 0ull; acc[h][1] = 0ull; }

    const float* zb = z + (size_t)i * 768 * 128 + lane * 4;
    for (int j = w; j < 768; j += 4) {
        float4 zv = __ldg((const float4*)(zb + (size_t)j * 128));
        ull zc01 = pack2(zv.x, zv.y);
        ull zc23 = pack2(zv.z, zv.w);
        const float* ar = &s_a[j * 12];
        float4 a0 = *(const float4*)ar;
        float4 a1 = *(const float4*)(ar + 4);
        float4 a2 = *(const float4*)(ar + 8);
        float av[12] = {a0.x, a0.y, a0.z, a0.w, a1.x, a1.y, a1.z, a1.w, a2.x, a2.y, a2.z, a2.w};
        #pragma unroll
        for (int h = 0; h < 12; h++) {
            ull d = pack2(av[h], av[h]);
            ffma2(acc[h][0], d, zc01);
            ffma2(acc[h][1], d, zc23);
        }
    }

    // write partials, reduce across 4 warps
    #pragma unroll
    for (int h = 0; h < 12; h++) {
        float2 u0 = unpack2(acc[h][0]), u1 = unpack2(acc[h][1]);
        float* p = &s_part[(w * 12 + h) * 128 + lane * 4];
        p[0] = u0.x; p[1] = u0.y; p[2] = u1.x; p[3] = u1.y;
    }
    __syncthreads();

    for (int idx = t; idx < 1536; idx += 128) {
        int h = idx >> 7, c = idx & 127;
        float s = s_part[(0 * 12 + h) * 128 + c] + s_part[(1 * 12 + h) * 128 + c]
                + s_part[(2 * 12 + h) * 128 + c] + s_part[(3 * 12 + h) * 128 + c];
        g_feats[(size_t)i * FEAT_N + 576 + h * 128 + c] = s;
    }
}

// ---------------- ov: o = a@v, o_pt(global) = a@v_pts (a is normalized) ----------------
__global__ __launch_bounds__(256) void ov_kernel()
{
    __shared__ float s_a[64 * 64];
    __shared__ float s_v[64 * 40];

    const int i0 = blockIdx.x * 64;
    const int h  = blockIdx.y;
    const int t = threadIdx.x;
    const int ig = t >> 3;
    const int og = t & 7;

    float acc[2][5] = {};

    for (int j0 = 0; j0 < 768; j0 += 64) {
        #pragma unroll
        for (int it = 0; it < 4; it++) {
            int idx = t + it * 256;
            int row = idx >> 4, q = idx & 15;
            float4 av = *(const float4*)&g_a[((size_t)(i0 + row) * 12 + h) * 768 + j0 + q * 4];
            *(float4*)&s_a[row * 64 + q * 4] = av;
        }
        #pragma unroll
        for (int it = 0; it < 10; it++) {
            int idx = t + it * 256;
            int jj = idx / 40, e = idx - jj * 40;
            s_v[idx] = (e < 16) ? g_v[(j0 + jj) * 192 + h * 16 + e]
                                : g_vpts[(j0 + jj) * 288 + h * 24 + (e - 16)];
        }
        __syncthreads();
        #pragma unroll 4
        for (int jj = 0; jj < 64; jj++) {
            float a0 = s_a[(ig * 2 + 0) * 64 + jj];
            float a1 = s_a[(ig * 2 + 1) * 64 + jj];
            const float* vp = &s_v[jj * 40 + og * 5];
            #pragma unroll
            for (int u = 0; u < 5; u++) {
                float vv = vp[u];
                acc[0][u] += a0 * vv;
                acc[1][u] += a1 * vv;
            }
        }
        __syncthreads();
    }
    #pragma unroll
    for (int r = 0; r < 2; r++) {
        int n = i0 + ig * 2 + r;
        #pragma unroll
        for (int u = 0; u < 5; u++) {
            int e = og * 5 + u;
            if (e < 16) g_feats[(size_t)n * FEAT_N + h * 16 + e] = acc[r][u];
            else        g_optg[n * 288 + h * 24 + (e - 16)] = acc[r][u];
        }
    }
}

// ---------------- optfinal ----------------
__global__ __launch_bounds__(96) void optfinal_kernel(
    const float* __restrict__ rot, const float* __restrict__ trans)
{
    const int n = blockIdx.x;
    const int hp = threadIdx.x;
    float r[9], tr[3];
    #pragma unroll
    for (int e = 0; e < 9; e++) r[e] = rot[n * 9 + e];
    tr[0] = trans[n * 3 + 0]; tr[1] = trans[n * 3 + 1]; tr[2] = trans[n * 3 + 2];

    float gx = g_optg[n * 288 + hp * 3 + 0] - tr[0];
    float gy = g_optg[n * 288 + hp * 3 + 1] - tr[1];
    float gz = g_optg[n * 288 + hp * 3 + 2] - tr[2];
    float l0 = r[0] * gx + r[3] * gy + r[6] * gz;
    float l1 = r[1] * gx + r[4] * gy + r[7] * gz;
    float l2 = r[2] * gx + r[5] * gy + r[8] * gz;

    float* f = &g_feats[(size_t)n * FEAT_N];
    f[192 + hp] = l0;
    f[288 + hp] = l1;
    f[384 + hp] = l2;
    f[480 + hp] = sqrtf(l0 * l0 + l1 * l1 + l2 * l2 + 1e-8f);
}

// ---------------- launch ----------------
extern "C" void kernel_launch(void* const* d_in, const int* in_sizes, int n_in,
                              void* d_out, int out_size)
{
    const float* s       = (const float*)d_in[0];
    const float* z       = (const float*)d_in[1];
    const float* rot     = (const float*)d_in[2];
    const float* trans   = (const float*)d_in[3];
    const float* mask    = (const float*)d_in[4];
    const float* ss      = (const float*)d_in[5];
    const float* w_q     = (const float*)d_in[6];
    const float* b_q     = (const float*)d_in[7];
    const float* w_kv    = (const float*)d_in[8];
    const float* b_kv    = (const float*)d_in[9];
    const float* w_qp    = (const float*)d_in[10];
    const float* b_qp    = (const float*)d_in[11];
    const float* w_kvp   = (const float*)d_in[12];
    const float* b_kvp   = (const float*)d_in[13];
    const float* w_b     = (const float*)d_in[14];
    const float* b_b     = (const float*)d_in[15];
    const float* head_w  = (const float*)d_in[16];
    const float* w_out   = (const float*)d_in[17];
    const float* b_out   = (const float*)d_in[18];
    float* out = (float*)d_out;

    float* proj;  cudaGetSymbolAddress((void**)&proj, g_proj);
    float* feats; cudaGetSymbolAddress((void**)&feats, g_feats);

    static bool attr_done = false;
    if (!attr_done) {
        cudaFuncSetAttribute(opair_kernel,
                             cudaFuncAttributeMaxDynamicSharedMemorySize,
                             OP_SMEM_FLOATS * 4);
        attr_done = true;
    }

    // K1: projections (768 x 1152)
    gemm_kernel<<<dim3(18, 24), 256>>>(
        s, CS, w_q, w_kv, w_qp, w_kvp, b_q, b_kv, b_qp, b_kvp,
        192, 576, 720, 1152, proj, PROJ_N);

    // K2: split k/v, rotate points, build logit-GEMM rows
    prep_kernel<<<NN, 384>>>(rot, trans, head_w);

    // K2b: qk+pts+mask logits as 30-dim GEMM
    qkpts_kernel<<<dim3(12, 12, 12), 256>>>(mask);

    // K3: z-bias + softmax (z pass 1, direct LDG)
    biassoftmax_kernel<<<NN, 256>>>(z, ss, w_b, b_b);

    // K3b: o_pair (z pass 2, direct coalesced LDG)
    opair_kernel<<<NN, 128, OP_SMEM_FLOATS * 4>>>(z);

    // K4: o and o_pt accumulation
    ov_kernel<<<dim3(12, 12), 256>>>();

    // K5: finalize o_pt + norms
    optfinal_kernel<<<NN, 96>>>(rot, trans);

    // K6: output GEMM (768 x 384, K=2112)
    gemm_kernel<<<dim3(6, 24), 256>>>(
        feats, FEAT_N, w_out, w_out, w_out, w_out, b_out, b_out, b_out, b_out,
        384, 384, 384, 384, out, CS);
}